// round 11
// baseline (speedup 1.0000x reference)
#include <cuda_runtime.h>
#include <math.h>
#include <stdint.h>

// ------------------------------------------------------------------
// Scratch (device globals). Aliasing: d2<->h1hi, d1<->h1lo.
// Layout (floats):
//  h1hi 0, h1lo 67108864, h2hi 134217728, h2lo 167772160,
//  h3 201326592, ze 218103808, zq 220200960; total 222298112
// ------------------------------------------------------------------
__device__ float g_arena[222298112];
__device__ float g_wtp[32768];       // 1x1 SIMT [k][m]
__device__ float g_w1hi[6144];       // conv1  packed frag-major hi/lo
__device__ float g_w1lo[6144];
__device__ float g_w2hi[524288];     // conv2 packed
__device__ float g_w2lo[524288];
__device__ float g_w3hi[2097152];    // conv3 packed
__device__ float g_w3lo[2097152];
__device__ float g_wd1hi[262144];    // convT1 [par] packed (hi only)
__device__ float g_wd2hi[524288];    // convT2 [par] packed (hi only)
__device__ float g_vqe2[512];
__device__ float g_vqpart[256];

// ------------------------------------------------------------------
// Helpers
// ------------------------------------------------------------------
__device__ __forceinline__ float tf32r(float v) {
    uint32_t u;
    asm("cvt.rna.tf32.f32 %0, %1;" : "=r"(u) : "f"(v));
    return __uint_as_float(u);
}
__device__ __forceinline__ uint32_t smem_u32(const void* p) {
    uint32_t a;
    asm("{ .reg .u64 t; cvta.to.shared.u64 t, %1; cvt.u32.u64 %0, t; }"
        : "=r"(a) : "l"(p));
    return a;
}
__device__ __forceinline__ void cpasync16(uint32_t dst, const void* src) {
    asm volatile("cp.async.cg.shared.global [%0], [%1], 16;"
                 :: "r"(dst), "l"(src));
}
__device__ __forceinline__ void cpasync4z(uint32_t dst, const void* src,
                                          uint32_t sz) {
    asm volatile("cp.async.ca.shared.global [%0], [%1], 4, %2;"
                 :: "r"(dst), "l"(src), "r"(sz));
}
#define CP_COMMIT() asm volatile("cp.async.commit_group;" ::: "memory")
#define CP_WAIT1()  asm volatile("cp.async.wait_group 1;" ::: "memory")
#define CP_WAIT0()  asm volatile("cp.async.wait_group 0;" ::: "memory")

__device__ __forceinline__ void mma8(float* d, const float* a, const float* b) {
    asm volatile(
        "mma.sync.aligned.m16n8k8.row.col.f32.tf32.tf32.f32 "
        "{%0,%1,%2,%3},{%4,%5,%6,%7},{%8,%9},{%0,%1,%2,%3};"
        : "+f"(d[0]), "+f"(d[1]), "+f"(d[2]), "+f"(d[3])
        : "r"(__float_as_uint(a[0])), "r"(__float_as_uint(a[1])),
          "r"(__float_as_uint(a[2])), "r"(__float_as_uint(a[3])),
          "r"(__float_as_uint(b[0])), "r"(__float_as_uint(b[1])));
}

// fragment-major pack offset within a (128m x 16k) block of A.
__device__ __forceinline__ int packoff(int mr, int kk) {
    int wmh = mr >> 6, mi = (mr >> 4) & 3, r8 = (mr >> 3) & 1, gp = mr & 7;
    int ks = kk >> 3, j2 = (kk >> 2) & 1, tg = kk & 3;
    return ((((wmh * 2 + ks) * 4 + mi) * 32) + gp * 4 + tg) * 4 + (r8 + 2 * j2);
}

// ------------------------------------------------------------------
// Weight transforms (2 launches total)
// ------------------------------------------------------------------
__global__ void xform_misc(const float* __restrict__ ew1, float* __restrict__ w1hi,
                           float* __restrict__ w1lo,
                           const float* __restrict__ pw, float* __restrict__ wtp,
                           const float* __restrict__ dw1, float* __restrict__ wd1hi,
                           const float* __restrict__ dw2, float* __restrict__ wd2hi,
                           const float* __restrict__ emb, float* __restrict__ e2) {
    int idx = blockIdx.x * 256 + threadIdx.x;
    if (idx < 6144) {                       // conv1: Cout=128, K=48
        int m = idx / 48, k = idx - m * 48;
        float v = ew1[idx];
        float h = tf32r(v);
        int dest = (k >> 4) * 2048 + packoff(m & 127, k & 15);
        w1hi[dest] = h;
        w1lo[dest] = tf32r(v - h);
    } else if (idx < 38912) {               // 1x1: Cout=64, CK=512
        int i = idx - 6144;
        int co = i / 512, k = i - co * 512;
        wtp[k * 64 + co] = pw[i];
    } else if (idx < 301056) {              // convT1: Cin=64, Cout=256, K=256
        int i = idx - 38912;
        int par = i >> 16, rem = i & 65535;
        int o = rem >> 8, kidx = rem & 255;
        int ci = kidx >> 2, dh = (kidx >> 1) & 1, dw = kidx & 1;
        int py = par >> 1, px = par & 1;
        int kh = 2 * dh + 1 - py, kw = 2 * dw + 1 - px;
        float v = dw1[((ci * 256 + o) * 4 + kh) * 4 + kw];
        int dest = par * 65536 + ((o >> 7) * 16 + (kidx >> 4)) * 2048 +
                   packoff(o & 127, kidx & 15);
        wd1hi[dest] = tf32r(v);
    } else if (idx < 825344) {              // convT2: Cin=256, Cout=128, K=1024
        int i = idx - 301056;
        int par = i >> 17, rem = i & 131071;
        int o = rem >> 10, kidx = rem & 1023;
        int ci = kidx >> 2, dh = (kidx >> 1) & 1, dw = kidx & 1;
        int py = par >> 1, px = par & 1;
        int kh = 2 * dh + 1 - py, kw = 2 * dw + 1 - px;
        float v = dw2[((ci * 128 + o) * 4 + kh) * 4 + kw];
        int dest = par * 131072 + (kidx >> 4) * 2048 + packoff(o, kidx & 15);
        wd2hi[dest] = tf32r(v);
    } else if (idx < 825856) {              // e2
        int c = idx - 825344;
        float s = 0.f;
        for (int d = 0; d < 64; d++) {
            float e = emb[c * 64 + d];
            s += e * e;
        }
        e2[c] = s;
    }
}

__global__ void pack_fwd(const float* __restrict__ ew2, float* __restrict__ w2hi,
                         float* __restrict__ w2lo,
                         const float* __restrict__ ew3, float* __restrict__ w3hi,
                         float* __restrict__ w3lo) {
    int idx = blockIdx.x * 256 + threadIdx.x;
    if (idx < 524288) {
        int m = idx >> 11, k = idx & 2047;
        float v = ew2[idx];
        float h = tf32r(v);
        int dest = ((m >> 7) * 128 + (k >> 4)) * 2048 + packoff(m & 127, k & 15);
        w2hi[dest] = h;
        w2lo[dest] = tf32r(v - h);
    } else if (idx < 524288 + 2097152) {
        int i = idx - 524288;
        int m = i >> 12, k = i & 4095;
        float v = ew3[i];
        float h = tf32r(v);
        int dest = ((m >> 7) * 256 + (k >> 4)) * 2048 + packoff(m & 127, k & 15);
        w3hi[dest] = h;
        w3lo[dest] = tf32r(v - h);
    }
}

// ------------------------------------------------------------------
// Warp-MMA tf32 implicit GEMM, fully-async 3-stage pipeline.
//   C[m][p] = sum_k W[m][k]*X[p][k]
// BM=128, BN=128, BK=16; 8 warps (2x4), warp tile 64x32.
// BPRE=1: B activations pre-split (SPLITS=3: xhi+xlo arrays) or
//         pre-rounded (SPLITS=1); consumer does ZERO converts.
// BPRE=0: raw B, consumer converts (conv1 only).
// EPI: 1=relu, 2=relu+split-write(out=hi,out2=lo), 3=relu+round.
// MODE 0: stride-2 4x4 conv; MODE 2: convT parity (par=blockIdx.z).
// ------------------------------------------------------------------
struct MP {
    const float* x;
    const float* xlo;
    const float* whi;
    const float* wlo;
    const float* bias;
    float* out;
    float* out2;
    int Cin, Hin, Win, Mtot, Hout, Wout, K, sHWo, sW;
};

template <int MODE, int SPLITS, int BPRE, int EPI>
__global__ __launch_bounds__(256, 2) void mma_igemm(MP g) {
    extern __shared__ __align__(16) float sm[];
    constexpr int LDB = 136;
    constexpr int ABLK = (SPLITS == 3) ? 4096 : 2048;
    constexpr int BHI = ABLK;
    constexpr int BLO = ABLK + 16 * LDB;
    constexpr int STAGE =
        ABLK + ((SPLITS == 3 && BPRE) ? 2 : 1) * 16 * LDB;

    const int t = threadIdx.x;
    const int lane = t & 31;
    const int wid = t >> 5;
    const int p0 = blockIdx.x * 128;
    const int m0 = blockIdx.y * 128;
    const int par = (MODE == 2) ? blockIdx.z : 0;
    const int py = par >> 1, px = par & 1;
    const uint32_t sbase = smem_u32(sm);
    const float* __restrict__ whiP =
        g.whi + (size_t)par * g.Mtot * g.K +
        ((size_t)(m0 >> 7) * (g.K >> 4)) * 2048;
    const float* __restrict__ wloP =
        (SPLITS == 3)
            ? g.wlo + ((size_t)(m0 >> 7) * (g.K >> 4)) * 2048
            : whiP;

    // B loader role
    const int lm = t & 127;
    const int kq = (t >> 7) * 8;

    // im2col decode for p = p0 + lm
    const int p = p0 + lm;
    const int n = p >> g.sHWo;
    const int rem = p & ((1 << g.sHWo) - 1);
    const int ho = rem >> g.sW, wo = rem & ((1 << g.sW) - 1);
    const size_t nOff = (size_t)n * g.Cin * g.Hin * g.Win;
    const float* __restrict__ xnh = g.x + nOff;
    const float* __restrict__ xnl = g.xlo + nOff;
    const int HW = g.Hin * g.Win;

    int rowoff[4], iwv[4];
    bool okh[4], okw[4];
    if (MODE == 0) {
#pragma unroll
        for (int kh = 0; kh < 4; kh++) {
            int ih = 2 * ho - 1 + kh;
            okh[kh] = (unsigned)ih < (unsigned)g.Hin;
            rowoff[kh] = ih * g.Win;
        }
#pragma unroll
        for (int kw = 0; kw < 4; kw++) {
            int iw = 2 * wo - 1 + kw;
            okw[kw] = (unsigned)iw < (unsigned)g.Win;
            iwv[kw] = iw;
        }
    } else {
#pragma unroll
        for (int dh = 0; dh < 2; dh++) {
            int ih = ho + py - dh;
            okh[dh] = (unsigned)ih < (unsigned)g.Hin;
            rowoff[dh] = ih * g.Win;
        }
#pragma unroll
        for (int dw = 0; dw < 2; dw++) {
            int iw = wo + px - dw;
            okw[dw] = (unsigned)iw < (unsigned)g.Win;
            iwv[dw] = iw;
        }
    }

    const int wmh = wid >> 2;
    const int wn = (wid & 3) * 32;
    const int gp = lane >> 2;
    const int tg = lane & 3;

    float acc[4][4][4];
#pragma unroll
    for (int mi = 0; mi < 4; mi++)
#pragma unroll
        for (int ni = 0; ni < 4; ni++)
#pragma unroll
            for (int r = 0; r < 4; r++) acc[mi][ni][r] = 0.f;

    auto issueAB = [&](int c, int s) {
        // A (packed, 16B)
        uint32_t da = sbase + (uint32_t)(s * STAGE + t * 8) * 4;
        const float* srcH = whiP + (size_t)c * 2048 + t * 8;
        cpasync16(da, srcH);
        cpasync16(da + 16, srcH + 4);
        if (SPLITS == 3) {
            uint32_t d2 = sbase + (uint32_t)(s * STAGE + 2048 + t * 8) * 4;
            const float* srcL = wloP + (size_t)c * 2048 + t * 8;
            cpasync16(d2, srcL);
            cpasync16(d2 + 16, srcL + 4);
        }
        // B (gather, 4B, zero-fill OOB)
        uint32_t dhi = sbase + (uint32_t)(s * STAGE + BHI) * 4;
        uint32_t dlo = sbase + (uint32_t)(s * STAGE + BLO) * 4;
        if (MODE == 0) {
#pragma unroll
            for (int j = 0; j < 8; j++) {
                int tap = kq + j;
                int kh = tap >> 2, kw = tap & 3;
                bool ok = okh[kh] && okw[kw];
                int off = ok ? rowoff[kh] + iwv[kw] : 0;
                uint32_t sz = ok ? 4u : 0u;
                uint32_t dst = (uint32_t)(tap * LDB + lm) * 4;
                cpasync4z(dhi + dst, xnh + (size_t)c * HW + off, sz);
                if (SPLITS == 3 && BPRE)
                    cpasync4z(dlo + dst, xnl + (size_t)c * HW + off, sz);
            }
        } else {
#pragma unroll
            for (int j = 0; j < 8; j++) {
                int tap = kq + j;
                int cl = tap >> 2, dd = tap & 3;
                int dh = dd >> 1, dw = dd & 1;
                bool ok = okh[dh] && okw[dw];
                size_t off = (size_t)(c * 4 + cl) * HW +
                             (ok ? rowoff[dh] + iwv[dw] : 0);
                uint32_t sz = ok ? 4u : 0u;
                uint32_t dst = (uint32_t)(tap * LDB + lm) * 4;
                cpasync4z(dhi + dst, xnh + off, sz);
                if (SPLITS == 3 && BPRE) cpasync4z(dlo + dst, xnl + off, sz);
            }
        }
        CP_COMMIT();
    };

    auto compute = [&](int s) {
        const float* S = sm + s * STAGE;
        const float4* A4 = (const float4*)S;
#pragma unroll
        for (int ks = 0; ks < 2; ks++) {
            const int kb = ks * 8;
            float b[4][2], b2[4][2];
#pragma unroll
            for (int ni = 0; ni < 4; ni++) {
                int pc = wn + ni * 8 + gp;
                float r0 = S[BHI + (kb + tg) * LDB + pc];
                float r1 = S[BHI + (kb + tg + 4) * LDB + pc];
                if (BPRE) {
                    b[ni][0] = r0;
                    b[ni][1] = r1;
                    if (SPLITS == 3) {
                        b2[ni][0] = S[BLO + (kb + tg) * LDB + pc];
                        b2[ni][1] = S[BLO + (kb + tg + 4) * LDB + pc];
                    }
                } else {
                    b[ni][0] = tf32r(r0);
                    b[ni][1] = tf32r(r1);
                    if (SPLITS == 3) {
                        b2[ni][0] = tf32r(r0 - b[ni][0]);
                        b2[ni][1] = tf32r(r1 - b[ni][1]);
                    }
                }
            }
#pragma unroll
            for (int mi = 0; mi < 4; mi++) {
                const int fidx = ((wmh * 2 + ks) * 4 + mi) * 32 + lane;
                float4 af = A4[fidx];
                float a[4] = {af.x, af.y, af.z, af.w};
#pragma unroll
                for (int ni = 0; ni < 4; ni++) mma8(acc[mi][ni], a, b[ni]);
                if (SPLITS == 3) {
                    float4 af2 = A4[fidx + 512];
                    float a2[4] = {af2.x, af2.y, af2.z, af2.w};
#pragma unroll
                    for (int ni = 0; ni < 4; ni++) mma8(acc[mi][ni], a2, b[ni]);
#pragma unroll
                    for (int ni = 0; ni < 4; ni++) mma8(acc[mi][ni], a, b2[ni]);
                }
            }
        }
    };

    const int nc = g.K >> 4;
    issueAB(0, 0);
    if (nc > 1) issueAB(1, 1);
    for (int c = 0; c < nc; c++) {
        if (c < nc - 1) CP_WAIT1(); else CP_WAIT0();
        __syncthreads();
        if (c + 2 < nc) issueAB(c + 2, (c + 2) % 3);
        compute(c % 3);
    }

    // epilogue
    const int HWo = 1 << g.sHWo;
    const int nn = p0 >> g.sHWo;
    const int rem0 = p0 & (HWo - 1);
#pragma unroll
    for (int mi = 0; mi < 4; mi++) {
        const int mA = m0 + wmh * 64 + mi * 16 + gp;
        const int mB = mA + 8;
        const float bA = g.bias[mA];
        const float bB = g.bias[mB];
#pragma unroll
        for (int ni = 0; ni < 4; ni++) {
            const int col = wn + ni * 8 + 2 * tg;
            float v0 = acc[mi][ni][0] + bA;
            float v1 = acc[mi][ni][1] + bA;
            float v2 = acc[mi][ni][2] + bB;
            float v3 = acc[mi][ni][3] + bB;
            if (EPI >= 1) {
                v0 = fmaxf(v0, 0.f); v1 = fmaxf(v1, 0.f);
                v2 = fmaxf(v2, 0.f); v3 = fmaxf(v3, 0.f);
            }
            if (MODE == 0) {
                size_t oA = ((size_t)nn * g.Mtot + mA) * HWo + rem0 + col;
                size_t oB = ((size_t)nn * g.Mtot + mB) * HWo + rem0 + col;
                if (EPI == 2) {
                    float h0 = tf32r(v0), h1 = tf32r(v1);
                    float h2v = tf32r(v2), h3v = tf32r(v3);
                    float2 qh0 = {h0, h1}, qh1 = {h2v, h3v};
                    *(float2*)&g.out[oA] = qh0;
                    *(float2*)&g.out[oB] = qh1;
                    float2 ql0 = {tf32r(v0 - h0), tf32r(v1 - h1)};
                    float2 ql1 = {tf32r(v2 - h2v), tf32r(v3 - h3v)};
                    *(float2*)&g.out2[oA] = ql0;
                    *(float2*)&g.out2[oB] = ql1;
                } else {
                    float2 q0 = {v0, v1}, q1 = {v2, v3};
                    *(float2*)&g.out[oA] = q0;
                    *(float2*)&g.out[oB] = q1;
                }
            } else {
                if (EPI == 3) {
                    v0 = tf32r(v0); v1 = tf32r(v1);
                    v2 = tf32r(v2); v3 = tf32r(v3);
                }
                int rr = rem0 + col;
                int hh = rr >> g.sW, ww = rr & ((1 << g.sW) - 1);
                size_t r0 = ((size_t)nn * g.Mtot + mA) * g.Hout + 2 * hh + py;
                g.out[r0 * g.Wout + 2 * ww + px] = v0;
                g.out[r0 * g.Wout + 2 * (ww + 1) + px] = v1;
                size_t r1 = ((size_t)nn * g.Mtot + mB) * g.Hout + 2 * hh + py;
                g.out[r1 * g.Wout + 2 * ww + px] = v2;
                g.out[r1 * g.Wout + 2 * (ww + 1) + px] = v3;
            }
        }
    }
}

// ------------------------------------------------------------------
// SIMT implicit GEMM (1x1 conv only)
// ------------------------------------------------------------------
struct GP {
    const float* x;
    const float* wt;
    const float* bias;
    float* out;
    int Cin, Hin, Win, M, K, sHWo, sW;
};

template <int ACT>
__global__ __launch_bounds__(256) void igemm1x1(GP g) {
    __shared__ __align__(16) float As[16][64];
    __shared__ __align__(16) float Bs[16][64];
    const int t = threadIdx.x;
    const int p0 = blockIdx.x * 64;
    const int m0 = blockIdx.y * 64;
    const int lc = t & 63, lr = t >> 6;
    const int tx = t & 15, ty = t >> 4;

    const int pB = p0 + lc;
    const int nB = pB >> g.sHWo;
    const int remB = pB & ((1 << g.sHWo) - 1);
    const float* __restrict__ xn = g.x + (size_t)nB * g.Cin * g.Hin * g.Win;

    float acc[4][4];
#pragma unroll
    for (int i = 0; i < 4; i++)
#pragma unroll
        for (int j = 0; j < 4; j++) acc[i][j] = 0.f;

    for (int k0 = 0; k0 < g.K; k0 += 16) {
#pragma unroll
        for (int j = 0; j < 4; j++) {
            int r = lr + 4 * j;
            As[r][lc] = g.wt[(size_t)(k0 + r) * g.M + m0 + lc];
            Bs[r][lc] = xn[(size_t)(k0 + r) * g.Win + remB];
        }
        __syncthreads();
#pragma unroll
        for (int kk = 0; kk < 16; kk++) {
            float4 a4 = *(const float4*)&As[kk][ty * 4];
            float4 b4 = *(const float4*)&Bs[kk][tx * 4];
            float av[4] = {a4.x, a4.y, a4.z, a4.w};
            float bv[4] = {b4.x, b4.y, b4.z, b4.w};
#pragma unroll
            for (int i = 0; i < 4; i++)
#pragma unroll
                for (int j = 0; j < 4; j++) acc[i][j] += av[i] * bv[j];
        }
        __syncthreads();
    }

    const int HWo = 1 << g.sHWo;
#pragma unroll
    for (int j = 0; j < 4; j++) {
        int p = p0 + tx * 4 + j;
        int nn = p >> g.sHWo;
        int rm = p & (HWo - 1);
#pragma unroll
        for (int i = 0; i < 4; i++) {
            int m = m0 + ty * 4 + i;
            float v = acc[i][j] + g.bias[m];
            if (ACT == 1) v = fmaxf(v, 0.f);
            g.out[((size_t)nn * g.M + m) * HWo + rm] = v;
        }
    }
}

// ------------------------------------------------------------------
// VQ (dot-product form) + loss; zq written tf32-pre-rounded
// ------------------------------------------------------------------
__global__ __launch_bounds__(128) void vq_kernel(
    const float* __restrict__ ze, const float* __restrict__ emb,
    const float* __restrict__ e2, float* __restrict__ zq,
    float* __restrict__ partial) {
    __shared__ float es[8192];
    __shared__ float e2s[128];
    __shared__ float red[128];
    const int t = threadIdx.x;
    const int pos = blockIdx.x * 128 + t;
    const int n = pos >> 10;
    const int hw = pos & 1023;

    float xv[64];
    const float* zp = ze + (size_t)n * 65536 + hw;
    float x2 = 0.f;
#pragma unroll
    for (int d = 0; d < 64; d++) {
        xv[d] = zp[(size_t)d * 1024];
        x2 += xv[d] * xv[d];
    }

    float best = 3.0e38f;
    int bidx = 0;
    for (int c0 = 0; c0 < 512; c0 += 128) {
        __syncthreads();
        {
            const float4* src = (const float4*)(emb + c0 * 64);
            float4* dst = (float4*)es;
            for (int i = t; i < 2048; i += 128) dst[i] = src[i];
            e2s[t] = e2[c0 + t];
        }
        __syncthreads();
        for (int c = 0; c < 128; c++) {
            float dot = 0.f;
            const float4* ep = (const float4*)(es + c * 64);
#pragma unroll
            for (int q = 0; q < 16; q++) {
                float4 e4 = ep[q];
                dot += xv[q * 4] * e4.x + xv[q * 4 + 1] * e4.y +
                       xv[q * 4 + 2] * e4.z + xv[q * 4 + 3] * e4.w;
            }
            float sc = e2s[c] - 2.f * dot;
            if (sc < best) { best = sc; bidx = c0 + c; }
        }
    }
    const float* e = emb + (size_t)bidx * 64;
    float* q = zq + (size_t)n * 65536 + hw;
#pragma unroll
    for (int d = 0; d < 64; d++) q[(size_t)d * 1024] = tf32r(e[d]);

    red[t] = x2 + best;
    __syncthreads();
    for (int s = 64; s > 0; s >>= 1) {
        if (t < s) red[t] += red[t + s];
        __syncthreads();
    }
    if (t == 0) partial[blockIdx.x] = red[0];
}

__global__ void vq_loss_kernel(const float* __restrict__ partial,
                               float* __restrict__ out_loss) {
    __shared__ float red[256];
    int t = threadIdx.x;
    red[t] = partial[t];
    __syncthreads();
    for (int s = 128; s > 0; s >>= 1) {
        if (t < s) red[t] += red[t + s];
        __syncthreads();
    }
    if (t == 0) out_loss[0] = red[0] * (2.0f / 2097152.0f);
}

// ------------------------------------------------------------------
// convT3 v2: smem-tiled direct + sigmoid
// ------------------------------------------------------------------
__global__ __launch_bounds__(256) void convt3_v2(
    const float* __restrict__ in, const float* __restrict__ w,
    const float* __restrict__ b, float* __restrict__ out) {
    extern __shared__ float s[];
    float* ws = s;             // 6144
    float* dat = s + 6144;     // 3*32*128 = 12288
    const int t = threadIdx.x;
    const int yq = blockIdx.y;
    const int n = blockIdx.z;
    for (int i = t; i < 6144; i += 256) ws[i] = w[i];

    const int py = t >> 7;
    const int xq = t & 127;
    float acc0[3], acc1[3];
#pragma unroll
    for (int ch = 0; ch < 3; ch++) { acc0[ch] = b[ch]; acc1[ch] = b[ch]; }

    const float* xn = in + (size_t)n * 2097152;
    for (int c0 = 0; c0 < 128; c0 += 32) {
        __syncthreads();
        for (int i = t; i < 12288; i += 256) {
            int r = i >> 12;
            int cc = (i >> 7) & 31;
            int wv = i & 127;
            int h = yq - 1 + r;
            dat[i] = ((unsigned)h < 128u)
                         ? xn[(size_t)(c0 + cc) * 16384 + h * 128 + wv] : 0.f;
        }
        __syncthreads();
        for (int cc = 0; cc < 32; cc++) {
            const float* wsc = ws + (c0 + cc) * 48;
#pragma unroll
            for (int dh = 0; dh < 2; dh++) {
                const int r = py + 1 - dh;
                const float* dr = dat + (r << 12) + (cc << 7);
                float v0 = dr[xq];
                float vm = (xq > 0) ? dr[xq - 1] : 0.f;
                float vp = (xq < 127) ? dr[xq + 1] : 0.f;
                const int kh = 2 * dh + 1 - py;
#pragma unroll
                for (int ch = 0; ch < 3; ch++) {
                    const float* wk = wsc + ch * 16 + kh * 4;
                    acc0[ch] += v0 * wk[1] + vm * wk[3];
                    acc1[ch] += vp * wk[0] + v0 * wk[2];
                }
            }
        }
    }
    const int y = 2 * yq + py;
#pragma unroll
    for (int ch = 0; ch < 3; ch++) {
        float2 q;
        q.x = 1.f / (1.f + expf(-acc0[ch]));
        q.y = 1.f / (1.f + expf(-acc1[ch]));
        *(float2*)&out[(((size_t)n * 3 + ch) << 16) + y * 256 + 2 * xq] = q;
    }
}

// ------------------------------------------------------------------
// Launch
// ------------------------------------------------------------------
extern "C" void kernel_launch(void* const* d_in, const int* in_sizes, int n_in,
                              void* d_out, int out_size) {
    (void)in_sizes; (void)n_in; (void)out_size;
    const float* x   = (const float*)d_in[0];
    const float* ew1 = (const float*)d_in[1];
    const float* eb1 = (const float*)d_in[2];
    const float* ew2 = (const float*)d_in[3];
    const float* eb2 = (const float*)d_in[4];
    const float* ew3 = (const float*)d_in[5];
    const float* eb3 = (const float*)d_in[6];
    const float* pw  = (const float*)d_in[7];
    const float* pb  = (const float*)d_in[8];
    const float* emb = (const float*)d_in[9];
    const float* dw1 = (const float*)d_in[10];
    const float* db1 = (const float*)d_in[11];
    const float* dw2 = (const float*)d_in[12];
    const float* db2 = (const float*)d_in[13];
    const float* dw3 = (const float*)d_in[14];
    const float* db3 = (const float*)d_in[15];
    float* out = (float*)d_out;

    float *arena, *wtp, *part, *e2;
    float *w1hi, *w1lo, *w2hi, *w2lo, *w3hi, *w3lo, *wd1hi, *wd2hi;
    cudaGetSymbolAddress((void**)&arena, g_arena);
    cudaGetSymbolAddress((void**)&wtp, g_wtp);
    cudaGetSymbolAddress((void**)&w1hi, g_w1hi);
    cudaGetSymbolAddress((void**)&w1lo, g_w1lo);
    cudaGetSymbolAddress((void**)&w2hi, g_w2hi);
    cudaGetSymbolAddress((void**)&w2lo, g_w2lo);
    cudaGetSymbolAddress((void**)&w3hi, g_w3hi);
    cudaGetSymbolAddress((void**)&w3lo, g_w3lo);
    cudaGetSymbolAddress((void**)&wd1hi, g_wd1hi);
    cudaGetSymbolAddress((void**)&wd2hi, g_wd2hi);
    cudaGetSymbolAddress((void**)&e2, g_vqe2);
    cudaGetSymbolAddress((void**)&part, g_vqpart);

    float* h1hi = arena;
    float* h1lo = arena + 67108864;
    float* h2hi = arena + 134217728;
    float* h2lo = arena + 167772160;
    float* h3   = arena + 201326592;
    float* ze   = arena + 218103808;
    float* zq   = arena + 220200960;
    float* d1b  = arena + 67108864;   // alias h1lo (dead after conv2)
    float* d2b  = arena;              // alias h1hi (dead after conv2)

    // smem: conv2/3 stage 8448 fl -> 3 st = 101376 B
    //       conv1 stage 6272 fl -> 3 st = 75264 B
    //       convT stage 4224 fl -> 3 st = 50688 B
    const int SM3P = 3 * 8448 * 4;
    const int SM3R = 3 * 6272 * 4;
    const int SM1  = 3 * 4224 * 4;
    const int SMT3 = (6144 + 12288) * 4;
    cudaFuncSetAttribute(mma_igemm<0, 3, 0, 2>,
                         cudaFuncAttributeMaxDynamicSharedMemorySize, SM3R);
    cudaFuncSetAttribute(mma_igemm<0, 3, 1, 2>,
                         cudaFuncAttributeMaxDynamicSharedMemorySize, SM3P);
    cudaFuncSetAttribute(mma_igemm<0, 3, 1, 1>,
                         cudaFuncAttributeMaxDynamicSharedMemorySize, SM3P);
    cudaFuncSetAttribute(mma_igemm<2, 1, 1, 3>,
                         cudaFuncAttributeMaxDynamicSharedMemorySize, SM1);
    cudaFuncSetAttribute(mma_igemm<2, 1, 1, 1>,
                         cudaFuncAttributeMaxDynamicSharedMemorySize, SM1);
    cudaFuncSetAttribute(convt3_v2,
                         cudaFuncAttributeMaxDynamicSharedMemorySize, SMT3);

    // 2 transform launches
    xform_misc<<<(825856 + 255) / 256, 256>>>(ew1, w1hi, w1lo, pw, wtp,
                                              dw1, wd1hi, dw2, wd2hi, emb, e2);
    pack_fwd<<<(2621440 + 255) / 256, 256>>>(ew2, w2hi, w2lo, ew3, w3hi, w3lo);

    MP m;
    // conv1 (3xTF32, raw B, split-write): x -> h1hi/h1lo
    m.x = x; m.xlo = x; m.whi = w1hi; m.wlo = w1lo; m.bias = eb1;
    m.out = h1hi; m.out2 = h1lo;
    m.Cin = 3; m.Hin = 256; m.Win = 256; m.Mtot = 128;
    m.Hout = 128; m.Wout = 128; m.K = 48; m.sHWo = 14; m.sW = 7;
    mma_igemm<0, 3, 0, 2><<<dim3(4096, 1), 256, SM3R>>>(m);

    // conv2 (3xTF32, pre-split B, split-write): h1 -> h2hi/h2lo
    m.x = h1hi; m.xlo = h1lo; m.whi = w2hi; m.wlo = w2lo; m.bias = eb2;
    m.out = h2hi; m.out2 = h2lo;
    m.Cin = 128; m.Hin = 128; m.Win = 128; m.Mtot = 256;
    m.Hout = 64; m.Wout = 64; m.K = 2048; m.sHWo = 12; m.sW = 6;
    mma_igemm<0, 3, 1, 2><<<dim3(1024, 2), 256, SM3P>>>(m);

    // conv3 (3xTF32, pre-split B): h2 -> h3 (plain fp32)
    m.x = h2hi; m.xlo = h2lo; m.whi = w3hi; m.wlo = w3lo; m.bias = eb3;
    m.out = h3; m.out2 = h3;
    m.Cin = 256; m.Hin = 64; m.Win = 64; m.Mtot = 512;
    m.Hout = 32; m.Wout = 32; m.K = 4096; m.sHWo = 10; m.sW = 5;
    mma_igemm<0, 3, 1, 1><<<dim3(256, 4), 256, SM3P>>>(m);

    // pre-VQ 1x1 (SIMT fp32): h3 -> ze
    GP g;
    g.x = h3; g.wt = wtp; g.bias = pb; g.out = ze;
    g.Cin = 512; g.Hin = 1; g.Win = 1024; g.M = 64;
    g.K = 512; g.sHWo = 10; g.sW = 0;
    igemm1x1<0><<<dim3(32768 / 64, 1), 256>>>(g);

    // VQ (zq pre-rounded tf32)
    vq_kernel<<<256, 128>>>(ze, emb, e2, zq, part);
    vq_loss_kernel<<<1, 256>>>(part, out + 6291456);

    // convT1 (1xTF32, pre-rounded B, round-write): zq -> d1
    m.x = zq; m.xlo = zq; m.whi = wd1hi; m.wlo = wd1hi; m.bias = db1;
    m.out = d1b; m.out2 = d1b;
    m.Cin = 64; m.Hin = 32; m.Win = 32; m.Mtot = 256;
    m.Hout = 64; m.Wout = 64; m.K = 256; m.sHWo = 10; m.sW = 5;
    mma_igemm<2, 1, 1, 3><<<dim3(256, 2, 4), 256, SM1>>>(m);

    // convT2 (1xTF32, pre-rounded B): d1 -> d2 (plain fp32)
    m.x = d1b; m.xlo = d1b; m.whi = wd2hi; m.wlo = wd2hi; m.bias = db2;
    m.out = d2b; m.out2 = d2b;
    m.Cin = 256; m.Hin = 64; m.Win = 64; m.Mtot = 128;
    m.Hout = 128; m.Wout = 128; m.K = 1024; m.sHWo = 12; m.sW = 6;
    mma_igemm<2, 1, 1, 1><<<dim3(1024, 1, 4), 256, SM1>>>(m);

    // convT3 v2 (smem-tiled) + sigmoid
    convt3_v2<<<dim3(1, 128, 32), 256, SMT3>>>(d2b, dw3, db3, out);
}

// round 13
// speedup vs baseline: 1.5541x; 1.5541x over previous
#include <cuda_runtime.h>
#include <cuda_fp16.h>
#include <math.h>
#include <stdint.h>

// ------------------------------------------------------------------
// Scratch. Arena aliasing: d1<->h2 (dead after conv3), d2<->h1.
// words: h1 0 (uint), h2 67108864 (uint), h3 100663296 (f32),
//        ze 117440512 (f32), zq 119537664 (uint); total 121634816
// ------------------------------------------------------------------
__device__ float g_arena[121634816];
__device__ uint32_t g_xsp[6291456];     // x pre-split half2
__device__ float g_wtp[32768];          // 1x1 SIMT [k][m]
__device__ __half g_w1hi[6144];         // conv1 packed frag-major
__device__ __half g_w1lo[6144];
__device__ __half g_w2hi[524288];       // conv2
__device__ __half g_w2lo[524288];
__device__ __half g_w3hi[2097152];      // conv3
__device__ __half g_w3lo[2097152];
__device__ __half g_wd1[262144];        // convT1 [par] (hi only)
__device__ __half g_wd2[524288];        // convT2 [par] (hi only)
__device__ float g_vqe2[512];
__device__ float g_vqpart[256];

// ------------------------------------------------------------------
// Helpers
// ------------------------------------------------------------------
__device__ __forceinline__ uint32_t smem_u32(const void* p) {
    uint32_t a;
    asm("{ .reg .u64 t; cvta.to.shared.u64 t, %1; cvt.u32.u64 %0, t; }"
        : "=r"(a) : "l"(p));
    return a;
}
__device__ __forceinline__ void cpasync16(uint32_t dst, const void* src) {
    asm volatile("cp.async.cg.shared.global [%0], [%1], 16;"
                 :: "r"(dst), "l"(src));
}
__device__ __forceinline__ void cpasync4z(uint32_t dst, const void* src,
                                          uint32_t sz) {
    asm volatile("cp.async.ca.shared.global [%0], [%1], 4, %2;"
                 :: "r"(dst), "l"(src), "r"(sz));
}
#define CP_COMMIT() asm volatile("cp.async.commit_group;" ::: "memory")
#define CP_WAIT1()  asm volatile("cp.async.wait_group 1;" ::: "memory")
#define CP_WAIT0()  asm volatile("cp.async.wait_group 0;" ::: "memory")

// m16n8k16 fp16 mma, f32 accum
__device__ __forceinline__ void mma16(float* d, const uint32_t* a,
                                      const uint32_t* b) {
    asm volatile(
        "mma.sync.aligned.m16n8k16.row.col.f32.f16.f16.f32 "
        "{%0,%1,%2,%3},{%4,%5,%6,%7},{%8,%9},{%0,%1,%2,%3};"
        : "+f"(d[0]), "+f"(d[1]), "+f"(d[2]), "+f"(d[3])
        : "r"(a[0]), "r"(a[1]), "r"(a[2]), "r"(a[3]),
          "r"(b[0]), "r"(b[1]));
}

// half2(hi,lo) split-pack of a float
__device__ __forceinline__ uint32_t packsplit(float v) {
    __half h = __float2half_rn(v);
    __half l = __float2half_rn(v - __half2float(h));
    return (uint32_t)__half_as_ushort(h) |
           ((uint32_t)__half_as_ushort(l) << 16);
}
__device__ __forceinline__ uint32_t packhi(float v) {
    return (uint32_t)__half_as_ushort(__float2half_rn(v));
}

// fragment-major pack: half-index of element (mr, kk) within a
// 128m x 16k block (2048 halves). Matches m16n8k16 A fragment:
// a_j for j = r8 + 2*(kk>=8); within-word pair tg=(kk&7)>>1, half kk&1.
__device__ __forceinline__ int packoffH(int mr, int kk) {
    int wmh = mr >> 6, mi = (mr >> 4) & 3, r8 = (mr >> 3) & 1, gp = mr & 7;
    int tg = (kk & 7) >> 1, khi = kk >> 3, h = kk & 1;
    int w = (((wmh * 4 + mi) * 32) + gp * 4 + tg) * 4 + (r8 + 2 * khi);
    return w * 2 + h;
}

// ------------------------------------------------------------------
// Weight transforms (2 launches total)
// ------------------------------------------------------------------
__global__ void xform_misc(const float* __restrict__ ew1, __half* __restrict__ w1hi,
                           __half* __restrict__ w1lo,
                           const float* __restrict__ pw, float* __restrict__ wtp,
                           const float* __restrict__ dw1, __half* __restrict__ wd1,
                           const float* __restrict__ dw2, __half* __restrict__ wd2,
                           const float* __restrict__ emb, float* __restrict__ e2) {
    int idx = blockIdx.x * 256 + threadIdx.x;
    if (idx < 6144) {                       // conv1: Cout=128, K=48
        int m = idx / 48, k = idx - m * 48;
        float v = ew1[idx];
        __half h = __float2half_rn(v);
        int dest = (k >> 4) * 2048 + packoffH(m & 127, k & 15);
        w1hi[dest] = h;
        w1lo[dest] = __float2half_rn(v - __half2float(h));
    } else if (idx < 38912) {               // 1x1: Cout=64, CK=512
        int i = idx - 6144;
        int co = i / 512, k = i - co * 512;
        wtp[k * 64 + co] = pw[i];
    } else if (idx < 301056) {              // convT1: Cin=64, Cout=256, K=256
        int i = idx - 38912;
        int par = i >> 16, rem = i & 65535;
        int o = rem >> 8, kidx = rem & 255;
        int ci = kidx >> 2, dh = (kidx >> 1) & 1, dw = kidx & 1;
        int py = par >> 1, px = par & 1;
        int kh = 2 * dh + 1 - py, kw = 2 * dw + 1 - px;
        float v = dw1[((ci * 256 + o) * 4 + kh) * 4 + kw];
        int dest = par * 65536 + ((o >> 7) * 16 + (kidx >> 4)) * 2048 +
                   packoffH(o & 127, kidx & 15);
        wd1[dest] = __float2half_rn(v);
    } else if (idx < 825344) {              // convT2: Cin=256, Cout=128, K=1024
        int i = idx - 301056;
        int par = i >> 17, rem = i & 131071;
        int o = rem >> 10, kidx = rem & 1023;
        int ci = kidx >> 2, dh = (kidx >> 1) & 1, dw = kidx & 1;
        int py = par >> 1, px = par & 1;
        int kh = 2 * dh + 1 - py, kw = 2 * dw + 1 - px;
        float v = dw2[((ci * 128 + o) * 4 + kh) * 4 + kw];
        int dest = par * 131072 + (kidx >> 4) * 2048 + packoffH(o, kidx & 15);
        wd2[dest] = __float2half_rn(v);
    } else if (idx < 825856) {              // e2
        int c = idx - 825344;
        float s = 0.f;
        for (int d = 0; d < 64; d++) {
            float e = emb[c * 64 + d];
            s += e * e;
        }
        e2[c] = s;
    }
}

// conv2/conv3 pack + x pre-split
__global__ void pack_fwd(const float* __restrict__ ew2, __half* __restrict__ w2hi,
                         __half* __restrict__ w2lo,
                         const float* __restrict__ ew3, __half* __restrict__ w3hi,
                         __half* __restrict__ w3lo,
                         const float* __restrict__ x, uint32_t* __restrict__ xsp) {
    int idx = blockIdx.x * 256 + threadIdx.x;
    if (idx < 524288) {
        int m = idx >> 11, k = idx & 2047;
        float v = ew2[idx];
        __half h = __float2half_rn(v);
        int dest = ((m >> 7) * 128 + (k >> 4)) * 2048 + packoffH(m & 127, k & 15);
        w2hi[dest] = h;
        w2lo[dest] = __float2half_rn(v - __half2float(h));
    } else if (idx < 2621440) {
        int i = idx - 524288;
        int m = i >> 12, k = i & 4095;
        float v = ew3[i];
        __half h = __float2half_rn(v);
        int dest = ((m >> 7) * 256 + (k >> 4)) * 2048 + packoffH(m & 127, k & 15);
        w3hi[dest] = h;
        w3lo[dest] = __float2half_rn(v - __half2float(h));
    } else if (idx < 2621440 + 6291456) {
        int i = idx - 2621440;
        xsp[i] = packsplit(x[i]);
    }
}

// ------------------------------------------------------------------
// fp16 warp-MMA implicit GEMM, async 3-stage pipeline.
//   C[m][p] = sum_k W[m][k]*X[p][k]
// BM=128, BN=128, BK=16 (one m16n8k16 set per chunk); 8 warps.
// A: fragment-major packed fp16 (hi[,lo]) -> cp.async 16B.
// B: half2(hi,lo) words gathered via cp.async 4B (zero-fill OOB);
//    consumer repacks k-pairs with PRMT. SPLITS: 3 products or 1.
// EPI: 1=relu f32 out; 2=relu+half2-split out; 4=relu+half2(hi) out.
// MODE 0: stride-2 4x4 conv; MODE 2: convT parity (par=blockIdx.z).
// ------------------------------------------------------------------
struct MP {
    const uint32_t* x;      // half2 words
    const uint32_t* whi;    // b32 view of packed A hi
    const uint32_t* wlo;
    const float* bias;
    void* out;
    int Cin, Hin, Win, Mtot, Hout, Wout, K, sHWo, sW;
};

template <int MODE, int SPLITS, int EPI>
__global__ __launch_bounds__(256, 2) void mma_igemm(MP g) {
    extern __shared__ __align__(16) uint32_t smw[];
    constexpr int LDB = 132;
    constexpr int ABLK = (SPLITS == 3) ? 2048 : 1024;  // b32 words
    constexpr int STAGE = ABLK + 16 * LDB;             // 4160 / 3136

    const int t = threadIdx.x;
    const int lane = t & 31;
    const int wid = t >> 5;
    const int p0 = blockIdx.x * 128;
    const int m0 = blockIdx.y * 128;
    const int par = (MODE == 2) ? blockIdx.z : 0;
    const int py = par >> 1, px = par & 1;
    const uint32_t sbase = smem_u32(smw);
    const uint32_t* __restrict__ whiP =
        g.whi + (size_t)par * ((size_t)g.Mtot * g.K / 2) +
        ((size_t)(m0 >> 7) * (g.K >> 4)) * 1024;
    const uint32_t* __restrict__ wloP =
        (SPLITS == 3)
            ? g.wlo + ((size_t)(m0 >> 7) * (g.K >> 4)) * 1024
            : whiP;

    // B loader role
    const int lm = t & 127;
    const int kq = (t >> 7) * 8;

    // im2col decode for p = p0 + lm
    const int p = p0 + lm;
    const int n = p >> g.sHWo;
    const int rem = p & ((1 << g.sHWo) - 1);
    const int ho = rem >> g.sW, wo = rem & ((1 << g.sW) - 1);
    const uint32_t* __restrict__ xn =
        g.x + (size_t)n * g.Cin * g.Hin * g.Win;
    const int HW = g.Hin * g.Win;

    int rowoff[4], iwv[4];
    bool okh[4], okw[4];
    if (MODE == 0) {
#pragma unroll
        for (int kh = 0; kh < 4; kh++) {
            int ih = 2 * ho - 1 + kh;
            okh[kh] = (unsigned)ih < (unsigned)g.Hin;
            rowoff[kh] = ih * g.Win;
        }
#pragma unroll
        for (int kw = 0; kw < 4; kw++) {
            int iw = 2 * wo - 1 + kw;
            okw[kw] = (unsigned)iw < (unsigned)g.Win;
            iwv[kw] = iw;
        }
    } else {
#pragma unroll
        for (int dh = 0; dh < 2; dh++) {
            int ih = ho + py - dh;
            okh[dh] = (unsigned)ih < (unsigned)g.Hin;
            rowoff[dh] = ih * g.Win;
        }
#pragma unroll
        for (int dw = 0; dw < 2; dw++) {
            int iw = wo + px - dw;
            okw[dw] = (unsigned)iw < (unsigned)g.Win;
            iwv[dw] = iw;
        }
    }

    const int wmh = wid >> 2;
    const int wn = (wid & 3) * 32;
    const int gp = lane >> 2;
    const int tg = lane & 3;

    float acc[4][4][4];
#pragma unroll
    for (int mi = 0; mi < 4; mi++)
#pragma unroll
        for (int ni = 0; ni < 4; ni++)
#pragma unroll
            for (int r = 0; r < 4; r++) acc[mi][ni][r] = 0.f;

    auto issueAB = [&](int c, int s) {
        // A (packed fp16, 16B)
        uint32_t da = sbase + (uint32_t)(s * STAGE + t * 4) * 4;
        cpasync16(da, whiP + (size_t)c * 1024 + t * 4);
        if (SPLITS == 3) {
            uint32_t d2 = sbase + (uint32_t)(s * STAGE + 1024 + t * 4) * 4;
            cpasync16(d2, wloP + (size_t)c * 1024 + t * 4);
        }
        // B (gather half2 words)
        uint32_t db = sbase + (uint32_t)(s * STAGE + ABLK) * 4;
        if (MODE == 0) {
            const uint32_t* bp = xn + (size_t)c * HW;
#pragma unroll
            for (int j = 0; j < 8; j++) {
                int tap = kq + j;
                int kh = tap >> 2, kw = tap & 3;
                bool ok = okh[kh] && okw[kw];
                const uint32_t* src = bp + (ok ? rowoff[kh] + iwv[kw] : 0);
                cpasync4z(db + (uint32_t)(tap * LDB + lm) * 4, src,
                          ok ? 4u : 0u);
            }
        } else {
#pragma unroll
            for (int j = 0; j < 8; j++) {
                int tap = kq + j;
                int cl = tap >> 2, dd = tap & 3;
                int dh = dd >> 1, dw = dd & 1;
                bool ok = okh[dh] && okw[dw];
                const uint32_t* src = xn + (size_t)(c * 4 + cl) * HW +
                                      (ok ? rowoff[dh] + iwv[dw] : 0);
                cpasync4z(db + (uint32_t)(tap * LDB + lm) * 4, src,
                          ok ? 4u : 0u);
            }
        }
        CP_COMMIT();
    };

    auto compute = [&](int s) {
        const uint32_t* S = smw + s * STAGE;
        const uint4* A4 = (const uint4*)S;
        uint32_t bhi[4][2], blo[4][2];
#pragma unroll
        for (int ni = 0; ni < 4; ni++) {
            int pc = wn + ni * 8 + gp;
            uint32_t w0 = S[ABLK + (2 * tg) * LDB + pc];
            uint32_t w1 = S[ABLK + (2 * tg + 1) * LDB + pc];
            uint32_t w2 = S[ABLK + (2 * tg + 8) * LDB + pc];
            uint32_t w3 = S[ABLK + (2 * tg + 9) * LDB + pc];
            bhi[ni][0] = __byte_perm(w0, w1, 0x5410);
            bhi[ni][1] = __byte_perm(w2, w3, 0x5410);
            if (SPLITS == 3) {
                blo[ni][0] = __byte_perm(w0, w1, 0x7632);
                blo[ni][1] = __byte_perm(w2, w3, 0x7632);
            }
        }
#pragma unroll
        for (int mi = 0; mi < 4; mi++) {
            const int fidx = (wmh * 4 + mi) * 32 + lane;
            uint4 ah4 = A4[fidx];
            uint32_t ah[4] = {ah4.x, ah4.y, ah4.z, ah4.w};
#pragma unroll
            for (int ni = 0; ni < 4; ni++) mma16(acc[mi][ni], ah, bhi[ni]);
            if (SPLITS == 3) {
                uint4 al4 = A4[256 + fidx];
                uint32_t al[4] = {al4.x, al4.y, al4.z, al4.w};
#pragma unroll
                for (int ni = 0; ni < 4; ni++) mma16(acc[mi][ni], al, bhi[ni]);
#pragma unroll
                for (int ni = 0; ni < 4; ni++) mma16(acc[mi][ni], ah, blo[ni]);
            }
        }
    };

    const int nc = g.K >> 4;
    issueAB(0, 0);
    if (nc > 1) issueAB(1, 1);
    for (int c = 0; c < nc; c++) {
        if (c < nc - 1) CP_WAIT1(); else CP_WAIT0();
        __syncthreads();
        if (c + 2 < nc) issueAB(c + 2, (c + 2) % 3);
        compute(c % 3);
    }

    // epilogue
    const int HWo = 1 << g.sHWo;
    const int nn = p0 >> g.sHWo;
    const int rem0 = p0 & (HWo - 1);
#pragma unroll
    for (int mi = 0; mi < 4; mi++) {
        const int mA = m0 + wmh * 64 + mi * 16 + gp;
        const int mB = mA + 8;
        const float bA = g.bias[mA];
        const float bB = g.bias[mB];
#pragma unroll
        for (int ni = 0; ni < 4; ni++) {
            const int col = wn + ni * 8 + 2 * tg;
            float v0 = fmaxf(acc[mi][ni][0] + bA, 0.f);
            float v1 = fmaxf(acc[mi][ni][1] + bA, 0.f);
            float v2 = fmaxf(acc[mi][ni][2] + bB, 0.f);
            float v3 = fmaxf(acc[mi][ni][3] + bB, 0.f);
            if (MODE == 0) {
                size_t oA = ((size_t)nn * g.Mtot + mA) * HWo + rem0 + col;
                size_t oB = ((size_t)nn * g.Mtot + mB) * HWo + rem0 + col;
                if (EPI == 2) {
                    uint32_t* O = (uint32_t*)g.out;
                    uint2 qa = {packsplit(v0), packsplit(v1)};
                    uint2 qb = {packsplit(v2), packsplit(v3)};
                    *(uint2*)&O[oA] = qa;
                    *(uint2*)&O[oB] = qb;
                } else {
                    float* O = (float*)g.out;
                    float2 qa = {v0, v1}, qb = {v2, v3};
                    *(float2*)&O[oA] = qa;
                    *(float2*)&O[oB] = qb;
                }
            } else {
                int rr = rem0 + col;
                int hh = rr >> g.sW, ww = rr & ((1 << g.sW) - 1);
                size_t r0 = ((size_t)nn * g.Mtot + mA) * g.Hout + 2 * hh + py;
                size_t r1 = ((size_t)nn * g.Mtot + mB) * g.Hout + 2 * hh + py;
                if (EPI == 4) {
                    uint32_t* O = (uint32_t*)g.out;
                    O[r0 * g.Wout + 2 * ww + px] = packhi(v0);
                    O[r0 * g.Wout + 2 * (ww + 1) + px] = packhi(v1);
                    O[r1 * g.Wout + 2 * ww + px] = packhi(v2);
                    O[r1 * g.Wout + 2 * (ww + 1) + px] = packhi(v3);
                } else {
                    float* O = (float*)g.out;
                    O[r0 * g.Wout + 2 * ww + px] = v0;
                    O[r0 * g.Wout + 2 * (ww + 1) + px] = v1;
                    O[r1 * g.Wout + 2 * ww + px] = v2;
                    O[r1 * g.Wout + 2 * (ww + 1) + px] = v3;
                }
            }
        }
    }
}

// ------------------------------------------------------------------
// SIMT implicit GEMM (1x1 conv only, fp32)
// ------------------------------------------------------------------
struct GP {
    const float* x;
    const float* wt;
    const float* bias;
    float* out;
    int Cin, Hin, Win, M, K, sHWo, sW;
};

template <int ACT>
__global__ __launch_bounds__(256) void igemm1x1(GP g) {
    __shared__ __align__(16) float As[16][64];
    __shared__ __align__(16) float Bs[16][64];
    const int t = threadIdx.x;
    const int p0 = blockIdx.x * 64;
    const int m0 = blockIdx.y * 64;
    const int lc = t & 63, lr = t >> 6;
    const int tx = t & 15, ty = t >> 4;

    const int pB = p0 + lc;
    const int nB = pB >> g.sHWo;
    const int remB = pB & ((1 << g.sHWo) - 1);
    const float* __restrict__ xn = g.x + (size_t)nB * g.Cin * g.Hin * g.Win;

    float acc[4][4];
#pragma unroll
    for (int i = 0; i < 4; i++)
#pragma unroll
        for (int j = 0; j < 4; j++) acc[i][j] = 0.f;

    for (int k0 = 0; k0 < g.K; k0 += 16) {
#pragma unroll
        for (int j = 0; j < 4; j++) {
            int r = lr + 4 * j;
            As[r][lc] = g.wt[(size_t)(k0 + r) * g.M + m0 + lc];
            Bs[r][lc] = xn[(size_t)(k0 + r) * g.Win + remB];
        }
        __syncthreads();
#pragma unroll
        for (int kk = 0; kk < 16; kk++) {
            float4 a4 = *(const float4*)&As[kk][ty * 4];
            float4 b4 = *(const float4*)&Bs[kk][tx * 4];
            float av[4] = {a4.x, a4.y, a4.z, a4.w};
            float bv[4] = {b4.x, b4.y, b4.z, b4.w};
#pragma unroll
            for (int i = 0; i < 4; i++)
#pragma unroll
                for (int j = 0; j < 4; j++) acc[i][j] += av[i] * bv[j];
        }
        __syncthreads();
    }

    const int HWo = 1 << g.sHWo;
#pragma unroll
    for (int j = 0; j < 4; j++) {
        int p = p0 + tx * 4 + j;
        int nn = p >> g.sHWo;
        int rm = p & (HWo - 1);
#pragma unroll
        for (int i = 0; i < 4; i++) {
            int m = m0 + ty * 4 + i;
            float v = acc[i][j] + g.bias[m];
            if (ACT == 1) v = fmaxf(v, 0.f);
            g.out[((size_t)nn * g.M + m) * HWo + rm] = v;
        }
    }
}

// ------------------------------------------------------------------
// VQ (dot-product form) + loss; zq written as half2(hi,0) words
// ------------------------------------------------------------------
__global__ __launch_bounds__(128) void vq_kernel(
    const float* __restrict__ ze, const float* __restrict__ emb,
    const float* __restrict__ e2, uint32_t* __restrict__ zq,
    float* __restrict__ partial) {
    __shared__ float es[8192];
    __shared__ float e2s[128];
    __shared__ float red[128];
    const int t = threadIdx.x;
    const int pos = blockIdx.x * 128 + t;
    const int n = pos >> 10;
    const int hw = pos & 1023;

    float xv[64];
    const float* zp = ze + (size_t)n * 65536 + hw;
    float x2 = 0.f;
#pragma unroll
    for (int d = 0; d < 64; d++) {
        xv[d] = zp[(size_t)d * 1024];
        x2 += xv[d] * xv[d];
    }

    float best = 3.0e38f;
    int bidx = 0;
    for (int c0 = 0; c0 < 512; c0 += 128) {
        __syncthreads();
        {
            const float4* src = (const float4*)(emb + c0 * 64);
            float4* dst = (float4*)es;
            for (int i = t; i < 2048; i += 128) dst[i] = src[i];
            e2s[t] = e2[c0 + t];
        }
        __syncthreads();
        for (int c = 0; c < 128; c++) {
            float dot = 0.f;
            const float4* ep = (const float4*)(es + c * 64);
#pragma unroll
            for (int q = 0; q < 16; q++) {
                float4 e4 = ep[q];
                dot += xv[q * 4] * e4.x + xv[q * 4 + 1] * e4.y +
                       xv[q * 4 + 2] * e4.z + xv[q * 4 + 3] * e4.w;
            }
            float sc = e2s[c] - 2.f * dot;
            if (sc < best) { best = sc; bidx = c0 + c; }
        }
    }
    const float* e = emb + (size_t)bidx * 64;
    uint32_t* q = zq + (size_t)n * 65536 + hw;
#pragma unroll
    for (int d = 0; d < 64; d++) q[(size_t)d * 1024] = packhi(e[d]);

    red[t] = x2 + best;
    __syncthreads();
    for (int s = 64; s > 0; s >>= 1) {
        if (t < s) red[t] += red[t + s];
        __syncthreads();
    }
    if (t == 0) partial[blockIdx.x] = red[0];
}

__global__ void vq_loss_kernel(const float* __restrict__ partial,
                               float* __restrict__ out_loss) {
    __shared__ float red[256];
    int t = threadIdx.x;
    red[t] = partial[t];
    __syncthreads();
    for (int s = 128; s > 0; s >>= 1) {
        if (t < s) red[t] += red[t + s];
        __syncthreads();
    }
    if (t == 0) out_loss[0] = red[0] * (2.0f / 2097152.0f);
}

// ------------------------------------------------------------------
// convT3 v2: smem-tiled direct + sigmoid (d2 fp32)
// ------------------------------------------------------------------
__global__ __launch_bounds__(256) void convt3_v2(
    const float* __restrict__ in, const float* __restrict__ w,
    const float* __restrict__ b, float* __restrict__ out) {
    extern __shared__ float s[];
    float* ws = s;             // 6144
    float* dat = s + 6144;     // 3*32*128 = 12288
    const int t = threadIdx.x;
    const int yq = blockIdx.y;
    const int n = blockIdx.z;
    for (int i = t; i < 6144; i += 256) ws[i] = w[i];

    const int py = t >> 7;
    const int xq = t & 127;
    float acc0[3], acc1[3];
#pragma unroll
    for (int ch = 0; ch < 3; ch++) { acc0[ch] = b[ch]; acc1[ch] = b[ch]; }

    const float* xn = in + (size_t)n * 2097152;
    for (int c0 = 0; c0 < 128; c0 += 32) {
        __syncthreads();
        for (int i = t; i < 12288; i += 256) {
            int r = i >> 12;
            int cc = (i >> 7) & 31;
            int wv = i & 127;
            int h = yq - 1 + r;
            dat[i] = ((unsigned)h < 128u)
                         ? xn[(size_t)(c0 + cc) * 16384 + h * 128 + wv] : 0.f;
        }
        __syncthreads();
        for (int cc = 0; cc < 32; cc++) {
            const float* wsc = ws + (c0 + cc) * 48;
#pragma unroll
            for (int dh = 0; dh < 2; dh++) {
                const int r = py + 1 - dh;
                const float* dr = dat + (r << 12) + (cc << 7);
                float v0 = dr[xq];
                float vm = (xq > 0) ? dr[xq - 1] : 0.f;
                float vp = (xq < 127) ? dr[xq + 1] : 0.f;
                const int kh = 2 * dh + 1 - py;
#pragma unroll
                for (int ch = 0; ch < 3; ch++) {
                    const float* wk = wsc + ch * 16 + kh * 4;
                    acc0[ch] += v0 * wk[1] + vm * wk[3];
                    acc1[ch] += vp * wk[0] + v0 * wk[2];
                }
            }
        }
    }
    const int y = 2 * yq + py;
#pragma unroll
    for (int ch = 0; ch < 3; ch++) {
        float2 q;
        q.x = 1.f / (1.f + expf(-acc0[ch]));
        q.y = 1.f / (1.f + expf(-acc1[ch]));
        *(float2*)&out[(((size_t)n * 3 + ch) << 16) + y * 256 + 2 * xq] = q;
    }
}

// ------------------------------------------------------------------
// Launch
// ------------------------------------------------------------------
extern "C" void kernel_launch(void* const* d_in, const int* in_sizes, int n_in,
                              void* d_out, int out_size) {
    (void)in_sizes; (void)n_in; (void)out_size;
    const float* x   = (const float*)d_in[0];
    const float* ew1 = (const float*)d_in[1];
    const float* eb1 = (const float*)d_in[2];
    const float* ew2 = (const float*)d_in[3];
    const float* eb2 = (const float*)d_in[4];
    const float* ew3 = (const float*)d_in[5];
    const float* eb3 = (const float*)d_in[6];
    const float* pw  = (const float*)d_in[7];
    const float* pb  = (const float*)d_in[8];
    const float* emb = (const float*)d_in[9];
    const float* dw1 = (const float*)d_in[10];
    const float* db1 = (const float*)d_in[11];
    const float* dw2 = (const float*)d_in[12];
    const float* db2 = (const float*)d_in[13];
    const float* dw3 = (const float*)d_in[14];
    const float* db3 = (const float*)d_in[15];
    float* out = (float*)d_out;

    float *arena, *wtp, *part, *e2;
    uint32_t* xsp;
    __half *w1hi, *w1lo, *w2hi, *w2lo, *w3hi, *w3lo, *wd1, *wd2;
    cudaGetSymbolAddress((void**)&arena, g_arena);
    cudaGetSymbolAddress((void**)&xsp, g_xsp);
    cudaGetSymbolAddress((void**)&wtp, g_wtp);
    cudaGetSymbolAddress((void**)&w1hi, g_w1hi);
    cudaGetSymbolAddress((void**)&w1lo, g_w1lo);
    cudaGetSymbolAddress((void**)&w2hi, g_w2hi);
    cudaGetSymbolAddress((void**)&w2lo, g_w2lo);
    cudaGetSymbolAddress((void**)&w3hi, g_w3hi);
    cudaGetSymbolAddress((void**)&w3lo, g_w3lo);
    cudaGetSymbolAddress((void**)&wd1, g_wd1);
    cudaGetSymbolAddress((void**)&wd2, g_wd2);
    cudaGetSymbolAddress((void**)&e2, g_vqe2);
    cudaGetSymbolAddress((void**)&part, g_vqpart);

    uint32_t* h1 = (uint32_t*)arena;                    // half2 words
    uint32_t* h2 = (uint32_t*)(arena + 67108864);
    float* h3 = arena + 100663296;
    float* ze = arena + 117440512;
    uint32_t* zq = (uint32_t*)(arena + 119537664);
    uint32_t* d1b = (uint32_t*)(arena + 67108864);      // alias h2
    float* d2b = arena;                                 // alias h1

    // smem: enc stage 4160 w -> 3 st = 49920 B; dec 3136 w -> 37632 B
    const int SME = 3 * 4160 * 4;
    const int SMD = 3 * 3136 * 4;
    const int SMT3 = (6144 + 12288) * 4;
    cudaFuncSetAttribute(mma_igemm<0, 3, 2>,
                         cudaFuncAttributeMaxDynamicSharedMemorySize, SME);
    cudaFuncSetAttribute(mma_igemm<0, 3, 1>,
                         cudaFuncAttributeMaxDynamicSharedMemorySize, SME);
    cudaFuncSetAttribute(mma_igemm<2, 1, 4>,
                         cudaFuncAttributeMaxDynamicSharedMemorySize, SMD);
    cudaFuncSetAttribute(mma_igemm<2, 1, 1>,
                         cudaFuncAttributeMaxDynamicSharedMemorySize, SMD);
    cudaFuncSetAttribute(convt3_v2,
                         cudaFuncAttributeMaxDynamicSharedMemorySize, SMT3);

    // 2 transform launches
    xform_misc<<<(825856 + 255) / 256, 256>>>(ew1, w1hi, w1lo, pw, wtp,
                                              dw1, wd1, dw2, wd2, emb, e2);
    pack_fwd<<<(8912896 + 255) / 256, 256>>>(ew2, w2hi, w2lo, ew3, w3hi,
                                             w3lo, x, xsp);

    MP m;
    // conv1 (fp16 x2-split): xsp -> h1 (half2)
    m.x = xsp; m.whi = (const uint32_t*)w1hi; m.wlo = (const uint32_t*)w1lo;
    m.bias = eb1; m.out = h1;
    m.Cin = 3; m.Hin = 256; m.Win = 256; m.Mtot = 128;
    m.Hout = 128; m.Wout = 128; m.K = 48; m.sHWo = 14; m.sW = 7;
    mma_igemm<0, 3, 2><<<dim3(4096, 1), 256, SME>>>(m);

    // conv2: h1 -> h2 (half2)
    m.x = h1; m.whi = (const uint32_t*)w2hi; m.wlo = (const uint32_t*)w2lo;
    m.bias = eb2; m.out = h2;
    m.Cin = 128; m.Hin = 128; m.Win = 128; m.Mtot = 256;
    m.Hout = 64; m.Wout = 64; m.K = 2048; m.sHWo = 12; m.sW = 6;
    mma_igemm<0, 3, 2><<<dim3(1024, 2), 256, SME>>>(m);

    // conv3: h2 -> h3 (fp32)
    m.x = h2; m.whi = (const uint32_t*)w3hi; m.wlo = (const uint32_t*)w3lo;
    m.bias = eb3; m.out = h3;
    m.Cin = 256; m.Hin = 64; m.Win = 64; m.Mtot = 512;
    m.Hout = 32; m.Wout = 32; m.K = 4096; m.sHWo = 10; m.sW = 5;
    mma_igemm<0, 3, 1><<<dim3(256, 4), 256, SME>>>(m);

    // pre-VQ 1x1 (SIMT fp32): h3 -> ze
    GP g;
    g.x = h3; g.wt = wtp; g.bias = pb; g.out = ze;
    g.Cin = 512; g.Hin = 1; g.Win = 1024; g.M = 64;
    g.K = 512; g.sHWo = 10; g.sW = 0;
    igemm1x1<0><<<dim3(32768 / 64, 1), 256>>>(g);

    // VQ (zq as half2 words)
    vq_kernel<<<256, 128>>>(ze, emb, e2, zq, part);
    vq_loss_kernel<<<1, 256>>>(part, out + 6291456);

    // convT1 (fp16 1x): zq -> d1 (half2), 4 pars via grid z
    m.x = zq; m.whi = (const uint32_t*)wd1; m.wlo = (const uint32_t*)wd1;
    m.bias = db1; m.out = d1b;
    m.Cin = 64; m.Hin = 32; m.Win = 32; m.Mtot = 256;
    m.Hout = 64; m.Wout = 64; m.K = 256; m.sHWo = 10; m.sW = 5;
    mma_igemm<2, 1, 4><<<dim3(256, 2, 4), 256, SMD>>>(m);

    // convT2 (fp16 1x): d1 -> d2 (fp32), 4 pars via grid z
    m.x = d1b; m.whi = (const uint32_t*)wd2; m.wlo = (const uint32_t*)wd2;
    m.bias = db2; m.out = d2b;
    m.Cin = 256; m.Hin = 64; m.Win = 64; m.Mtot = 128;
    m.Hout = 128; m.Wout = 128; m.K = 1024; m.sHWo = 12; m.sW = 6;
    mma_igemm<2, 1, 1><<<dim3(1024, 1, 4), 256, SMD>>>(m);

    // convT3 v2 (smem-tiled) + sigmoid
    convt3_v2<<<dim3(1, 128, 32), 256, SMT3>>>(d2b, dw3, db3, out);
}